// round 8
// baseline (speedup 1.0000x reference)
#include <cuda_runtime.h>
#include <cuda_bf16.h>
#include <cstdint>
#include <math.h>

// Problem dims
#define BDIM 8192
#define CDIM 12
#define DIN  1024
#define DOUT 1024
#define ADIM 8
#define NDIM (CDIM * DOUT)   // 12288

// GEMM tiling
#define BK     32            // K per smem stage
#define APITCH 40            // padded row pitch (bf16 elems) -> 80 B, conflict-free ldmatrix

// ---------------- scratch (no allocations allowed -> device globals) --------
__device__ float g_u[(size_t)BDIM * NDIM];            // 402 MB
__device__ float g_Hb[BDIM];
__device__ __nv_bfloat16 g_xhi[(size_t)BDIM * DIN];   // 16 MB
__device__ __nv_bfloat16 g_xlo[(size_t)BDIM * DIN];   // 16 MB
__device__ __nv_bfloat16 g_Whi[(size_t)NDIM * DIN];   // 24 MB
__device__ __nv_bfloat16 g_Wlo[(size_t)NDIM * DIN];   // 24 MB

// ---------------- helpers ----------------------------------------------------
__device__ __forceinline__ uint32_t smem_u32(const void* p) {
    uint32_t a;
    asm("{ .reg .u64 t; cvta.to.shared.u64 t, %1; cvt.u32.u64 %0, t; }"
        : "=r"(a) : "l"(p));
    return a;
}

__device__ __forceinline__ void ldsm4(uint32_t r[4], uint32_t addr) {
    asm volatile("ldmatrix.sync.aligned.m8n8.x4.shared.b16 {%0,%1,%2,%3}, [%4];"
                 : "=r"(r[0]), "=r"(r[1]), "=r"(r[2]), "=r"(r[3])
                 : "r"(addr));
}

__device__ __forceinline__ void mma16816(float c[4], const uint32_t a[4],
                                         const uint32_t b0, const uint32_t b1) {
    asm volatile(
        "mma.sync.aligned.m16n8k16.row.col.f32.bf16.bf16.f32 "
        "{%0,%1,%2,%3}, {%4,%5,%6,%7}, {%8,%9}, {%0,%1,%2,%3};"
        : "+f"(c[0]), "+f"(c[1]), "+f"(c[2]), "+f"(c[3])
        : "r"(a[0]), "r"(a[1]), "r"(a[2]), "r"(a[3]), "r"(b0), "r"(b1));
}

// ---------------- convert: fp32 -> bf16 hi/lo --------------------------------
__device__ __forceinline__ uint32_t pack_bf2(__nv_bfloat16 a, __nv_bfloat16 b) {
    __nv_bfloat162 t(a, b);
    return *reinterpret_cast<uint32_t*>(&t);
}
__device__ __forceinline__ void split4(float4 v, uint2& H, uint2& L) {
    __nv_bfloat16 h0 = __float2bfloat16(v.x);
    __nv_bfloat16 h1 = __float2bfloat16(v.y);
    __nv_bfloat16 h2 = __float2bfloat16(v.z);
    __nv_bfloat16 h3 = __float2bfloat16(v.w);
    __nv_bfloat16 l0 = __float2bfloat16(v.x - __bfloat162float(h0));
    __nv_bfloat16 l1 = __float2bfloat16(v.y - __bfloat162float(h1));
    __nv_bfloat16 l2 = __float2bfloat16(v.z - __bfloat162float(h2));
    __nv_bfloat16 l3 = __float2bfloat16(v.w - __bfloat162float(h3));
    H.x = pack_bf2(h0, h1); H.y = pack_bf2(h2, h3);
    L.x = pack_bf2(l0, l1); L.y = pack_bf2(l2, l3);
}
__global__ void convert_x_kernel(const float* __restrict__ x) {
    int i = blockIdx.x * blockDim.x + threadIdx.x;   // over float4s
    float4 v = ((const float4*)x)[i];
    uint2 H, L;
    split4(v, H, L);
    ((uint2*)g_xhi)[i] = H;
    ((uint2*)g_xlo)[i] = L;
}
__global__ void convert_w_kernel(const float* __restrict__ W) {
    int i = blockIdx.x * blockDim.x + threadIdx.x;
    float4 v = ((const float4*)W)[i];
    uint2 H, L;
    split4(v, H, L);
    ((uint2*)g_Whi)[i] = H;
    ((uint2*)g_Wlo)[i] = L;
}

// ---------------- HMMA GEMM: u = x @ W^T + bias ------------------------------
// C[m,n] = sum_k A[m,k] * B[n,k];  A = x (hi/lo), B = W (hi/lo).
// CTA tile 128x128, 8 warps as 2(M) x 4(N), warp tile 64x32.
// mma.sync.m16n8k16 row.col bf16; 3 products (hh, hl, lh) for fp32 accuracy.
__global__ __launch_bounds__(256, 1)
void gemm_mma_kernel(const float* __restrict__ bias) {
    __shared__ __nv_bfloat16 sA[2][128 * APITCH];   // [hi/lo][128 x 40]
    __shared__ __nv_bfloat16 sB[2][128 * APITCH];

    const int tid  = threadIdx.x;
    const int lane = tid & 31;
    const int wid  = tid >> 5;
    const int wy   = wid >> 2;          // 0..1 (M)
    const int wx   = wid & 3;           // 0..3 (N)
    const int m0 = blockIdx.y * 128;
    const int n0 = blockIdx.x * 128;

    float acc[4][4][4];
#pragma unroll
    for (int mt = 0; mt < 4; mt++)
#pragma unroll
        for (int nt = 0; nt < 4; nt++)
#pragma unroll
            for (int q = 0; q < 4; q++) acc[mt][nt][q] = 0.0f;

    // global-load coordinates: 2 uint4 per thread per tile (128x32 bf16 = 512 uint4)
    int lr[2], lc[2];
#pragma unroll
    for (int j = 0; j < 2; j++) {
        int idx = tid + j * 256;        // 0..511
        lr[j] = idx >> 2;               // row 0..127
        lc[j] = (idx & 3) * 8;          // col 0,8,16,24 (bf16 elems)
    }

    const __nv_bfloat16* Ah = g_xhi + (size_t)m0 * DIN;
    const __nv_bfloat16* Al = g_xlo + (size_t)m0 * DIN;
    const __nv_bfloat16* Bh = g_Whi + (size_t)n0 * DIN;
    const __nv_bfloat16* Bl = g_Wlo + (size_t)n0 * DIN;

    // prologue: stage kt=0 in registers
    uint4 pAh[2], pAl[2], pBh[2], pBl[2];
#pragma unroll
    for (int j = 0; j < 2; j++) {
        size_t go = (size_t)lr[j] * DIN + lc[j];
        pAh[j] = *(const uint4*)(Ah + go);
        pAl[j] = *(const uint4*)(Al + go);
        pBh[j] = *(const uint4*)(Bh + go);
        pBl[j] = *(const uint4*)(Bl + go);
    }

    // per-warp ldmatrix smem addresses
    // A (x4): lanes 0-7 rows 0-7 @kk, 8-15 rows 8-15 @kk, 16-23 rows 0-7 @kk+8, 24-31 rows 8-15 @kk+8
    const int a_r   = wy * 64 + (lane & 15);
    const int a_c   = (lane >> 4) << 3;
    // B (x4): octet o: rows (o>=2 ? +8 : 0) + lane&7 ; col kk + (o&1)*8
    const int o     = lane >> 3;
    const int b_r   = wx * 32 + ((o >= 2) ? 8 : 0) + (lane & 7);
    const int b_c   = (o & 1) << 3;

    for (int kt = 0; kt < DIN; kt += BK) {
        // commit staged registers to smem
#pragma unroll
        for (int j = 0; j < 2; j++) {
            int so = lr[j] * APITCH + lc[j];
            *(uint4*)&sA[0][so] = pAh[j];
            *(uint4*)&sA[1][so] = pAl[j];
            *(uint4*)&sB[0][so] = pBh[j];
            *(uint4*)&sB[1][so] = pBl[j];
        }
        __syncthreads();

        // prefetch next stage (overlaps with compute below)
        if (kt + BK < DIN) {
#pragma unroll
            for (int j = 0; j < 2; j++) {
                size_t go = (size_t)lr[j] * DIN + kt + BK + lc[j];
                pAh[j] = *(const uint4*)(Ah + go);
                pAl[j] = *(const uint4*)(Al + go);
                pBh[j] = *(const uint4*)(Bh + go);
                pBl[j] = *(const uint4*)(Bl + go);
            }
        }

#pragma unroll
        for (int ks = 0; ks < 2; ks++) {
            const int kk = ks * 16;
            uint32_t ah[4][4], al[4][4];
#pragma unroll
            for (int mt = 0; mt < 4; mt++) {
                int off = (a_r + mt * 16) * APITCH + kk + a_c;
                ldsm4(ah[mt], smem_u32(&sA[0][off]));
                ldsm4(al[mt], smem_u32(&sA[1][off]));
            }
            uint32_t bh[4][2], bl[4][2];
#pragma unroll
            for (int p = 0; p < 2; p++) {   // n-tile pair p covers ntiles 2p, 2p+1
                int off = (b_r + p * 16) * APITCH + kk + b_c;
                uint32_t th[4], tl[4];
                ldsm4(th, smem_u32(&sB[0][off]));
                ldsm4(tl, smem_u32(&sB[1][off]));
                bh[2 * p][0] = th[0]; bh[2 * p][1] = th[1];
                bh[2 * p + 1][0] = th[2]; bh[2 * p + 1][1] = th[3];
                bl[2 * p][0] = tl[0]; bl[2 * p][1] = tl[1];
                bl[2 * p + 1][0] = tl[2]; bl[2 * p + 1][1] = tl[3];
            }
#pragma unroll
            for (int mt = 0; mt < 4; mt++) {
#pragma unroll
                for (int nt = 0; nt < 4; nt++) {
                    mma16816(acc[mt][nt], ah[mt], bh[nt][0], bh[nt][1]); // hi*hi
                    mma16816(acc[mt][nt], ah[mt], bl[nt][0], bl[nt][1]); // hi*lo
                    mma16816(acc[mt][nt], al[mt], bh[nt][0], bh[nt][1]); // lo*hi
                }
            }
        }
        __syncthreads();
    }

    // epilogue: c0=C[g][2i], c1=C[g][2i+1], c2=C[g+8][2i], c3=C[g+8][2i+1]
    const int g = lane >> 2;
    const int i4 = lane & 3;
#pragma unroll
    for (int nt = 0; nt < 4; nt++) {
        int n = n0 + wx * 32 + nt * 8 + i4 * 2;
        float2 bv = *(const float2*)&bias[n];
#pragma unroll
        for (int mt = 0; mt < 4; mt++) {
            int m = m0 + wy * 64 + mt * 16 + g;
            float2 r0 = make_float2(acc[mt][nt][0] + bv.x, acc[mt][nt][1] + bv.y);
            float2 r1 = make_float2(acc[mt][nt][2] + bv.x, acc[mt][nt][3] + bv.y);
            *(float2*)&g_u[(size_t)m * NDIM + n] = r0;
            *(float2*)&g_u[(size_t)(m + 8) * NDIM + n] = r1;
        }
    }
}

// ---------------- routing: one CTA (256 thr) per row b -----------------------
__global__ __launch_bounds__(256)
void routing_kernel(float* __restrict__ out) {
    const int b = blockIdx.x;
    const int t = threadIdx.x;
    const int lane = t & 31;
    const int warp = t >> 5;
    const int o0 = t * 4;

    const float* ur = g_u + (size_t)b * NDIM;

    float u[CDIM][4];
#pragma unroll
    for (int c = 0; c < CDIM; c++) {
        float4 v4 = *(const float4*)(ur + c * DOUT + o0);
        u[c][0] = v4.x; u[c][1] = v4.y; u[c][2] = v4.z; u[c][3] = v4.w;
    }

    __shared__ float blog[CDIM];
    __shared__ float sred[8 * CDIM];
    __shared__ float sone[8];
    __shared__ float sbc;

    if (t < CDIM) blog[t] = 0.0f;
    __syncthreads();

    float s[4];
    float vv[4];

    for (int it = 0; it < 3; it++) {
        float mx = blog[0];
#pragma unroll
        for (int c = 1; c < CDIM; c++) mx = fmaxf(mx, blog[c]);
        float e[CDIM];
        float se = 0.0f;
#pragma unroll
        for (int c = 0; c < CDIM; c++) { e[c] = expf(blog[c] - mx); se += e[c]; }
        float inv = 1.0f / se;

#pragma unroll
        for (int j = 0; j < 4; j++) s[j] = 0.0f;
#pragma unroll
        for (int c = 0; c < CDIM; c++) {
            float w = e[c] * inv;
#pragma unroll
            for (int j = 0; j < 4; j++) s[j] = fmaf(w, u[c][j], s[j]);
        }

        float ns = s[0] * s[0] + s[1] * s[1] + s[2] * s[2] + s[3] * s[3];
#pragma unroll
        for (int off = 16; off; off >>= 1) ns += __shfl_xor_sync(0xffffffffu, ns, off);
        if (lane == 0) sone[warp] = ns;
        __syncthreads();
        if (t == 0) {
            float tot = 0.0f;
            for (int w = 0; w < 8; w++) tot += sone[w];
            sbc = tot;
        }
        __syncthreads();
        float normsq = sbc;
        __syncthreads();

        float norm = sqrtf(normsq);
        float scale = normsq / (1.0f + normsq) / (norm + 1e-8f);
#pragma unroll
        for (int j = 0; j < 4; j++) vv[j] = scale * s[j];

        if (it < 2) {
            float part[CDIM];
#pragma unroll
            for (int c = 0; c < CDIM; c++)
                part[c] = u[c][0] * vv[0] + u[c][1] * vv[1] +
                          u[c][2] * vv[2] + u[c][3] * vv[3];
#pragma unroll
            for (int c = 0; c < CDIM; c++) {
#pragma unroll
                for (int off = 16; off; off >>= 1)
                    part[c] += __shfl_xor_sync(0xffffffffu, part[c], off);
            }
            if (lane == 0) {
#pragma unroll
                for (int c = 0; c < CDIM; c++) sred[warp * CDIM + c] = part[c];
            }
            __syncthreads();
            if (t < CDIM) {
                float tt = 0.0f;
                for (int w = 0; w < 8; w++) tt += sred[w * CDIM + t];
                blog[t] += tt;
            }
            __syncthreads();
        }
    }

    float4 vo = make_float4(vv[0], vv[1], vv[2], vv[3]);
#pragma unroll
    for (int a = 0; a < ADIM; a++)
        *(float4*)(out + ((size_t)b * ADIM + a) * DOUT + o0) = vo;

    float mx = fmaxf(fmaxf(s[0], s[1]), fmaxf(s[2], s[3]));
#pragma unroll
    for (int off = 16; off; off >>= 1)
        mx = fmaxf(mx, __shfl_xor_sync(0xffffffffu, mx, off));
    if (lane == 0) sone[warp] = mx;
    __syncthreads();
    if (t == 0) {
        float m = sone[0];
        for (int w = 1; w < 8; w++) m = fmaxf(m, sone[w]);
        sbc = m;
    }
    __syncthreads();
    mx = sbc;
    __syncthreads();

    float sume = expf(s[0] - mx) + expf(s[1] - mx) + expf(s[2] - mx) + expf(s[3] - mx);
#pragma unroll
    for (int off = 16; off; off >>= 1) sume += __shfl_xor_sync(0xffffffffu, sume, off);
    if (lane == 0) sone[warp] = sume;
    __syncthreads();
    if (t == 0) {
        float tot = 0.0f;
        for (int w = 0; w < 8; w++) tot += sone[w];
        sbc = tot;
    }
    __syncthreads();
    float S = sbc + 1e-10f;
    __syncthreads();

    float h = 0.0f;
#pragma unroll
    for (int j = 0; j < 4; j++) {
        float p = expf(s[j] - mx) / S;
        h -= p * logf(p + 1e-10f);
    }
#pragma unroll
    for (int off = 16; off; off >>= 1) h += __shfl_xor_sync(0xffffffffu, h, off);
    if (lane == 0) sone[warp] = h;
    __syncthreads();
    if (t == 0) {
        float tot = 0.0f;
        for (int w = 0; w < 8; w++) tot += sone[w];
        tot = fminf(fmaxf(tot, 0.0f), 10.0f);
        g_Hb[b] = tot;
    }
}

// ---------------- finalize: deterministic entropy mean + loss ----------------
__global__ void finalize_kernel(float* __restrict__ out, int out_size) {
    __shared__ float sh[256];
    float t = 0.0f;
    for (int i = threadIdx.x; i < BDIM; i += 256) t += g_Hb[i];
    sh[threadIdx.x] = t;
    __syncthreads();
    for (int s = 128; s > 0; s >>= 1) {
        if (threadIdx.x < s) sh[threadIdx.x] += sh[threadIdx.x + s];
        __syncthreads();
    }
    if (threadIdx.x == 0) {
        float mean = sh[0] / (float)BDIM;
        float loss = -0.4f / (1.0f + expf(-mean));
        out[out_size - 1] = loss;
    }
}

// ---------------- launch -----------------------------------------------------
extern "C" void kernel_launch(void* const* d_in, const int* in_sizes, int n_in,
                              void* d_out, int out_size) {
    const float* x    = (const float*)d_in[0];   // [8192, 1024]
    const float* W    = (const float*)d_in[1];   // [12, 1024, 1024]
    const float* bias = (const float*)d_in[2];   // [12, 1024]
    float* out = (float*)d_out;

    convert_x_kernel<<<(BDIM * DIN / 4) / 256, 256>>>(x);
    convert_w_kernel<<<(NDIM * DIN / 4) / 256, 256>>>(W);

    dim3 ggrid(NDIM / 128, BDIM / 128);          // (96, 64)
    gemm_mma_kernel<<<ggrid, 256>>>(bias);

    routing_kernel<<<BDIM, 256>>>(out);
    finalize_kernel<<<1, 256>>>(out, out_size);
}